// round 1
// baseline (speedup 1.0000x reference)
#include <cuda_runtime.h>
#include <math_constants.h>
#include <stdint.h>

#define BATCH 8
#define CH 256
#define HH 128
#define WW 128
#define HWSZ 16384
#define NPTS 500
#define NHID 16

// ---------------- scratch (device globals; no allocation allowed) ----------------
__device__ float g_score[BATCH * HWSZ];
__device__ int   g_idx[BATCH * NPTS];
__device__ float g_vmain[BATCH * NPTS * CH];
__device__ float g_vaux [BATCH * NPTS * CH];
__device__ float g_vinj [BATCH * NPTS * CH];

// ================= kernel 1: fused copy (out = x_main) + scorer logits =================
// grid 256 blocks x 128 threads; each thread owns 4 consecutive pixels (float4),
// loops all 256 channels: read once, write copy, accumulate score.
__global__ void k1_copy_score(const float* __restrict__ xm,
                              const float* __restrict__ sw,
                              float* __restrict__ out) {
    __shared__ float s_w[CH];
    int t = threadIdx.x;
    for (int i = t; i < CH; i += blockDim.x) s_w[i] = sw[i];
    __syncthreads();

    int gp = (blockIdx.x * 128 + t) * 4;     // global pixel index in [0, BATCH*HWSZ)
    int b  = gp >> 14;
    int hw = gp & (HWSZ - 1);
    const float4* src = reinterpret_cast<const float4*>(xm + (size_t)b * CH * HWSZ + hw);
    float4*       dst = reinterpret_cast<float4*>(out + (size_t)b * CH * HWSZ + hw);

    float a0 = 0.f, a1 = 0.f, a2 = 0.f, a3 = 0.f;
    #pragma unroll 4
    for (int c = 0; c < CH; ++c) {
        float4 v = src[c * (HWSZ / 4)];
        dst[c * (HWSZ / 4)] = v;
        float w = s_w[c];
        a0 += v.x * w; a1 += v.y * w; a2 += v.z * w; a3 += v.w * w;
    }
    *reinterpret_cast<float4*>(g_score + gp) = make_float4(a0, a1, a2, a3);
}

// ================= kernel 2: exact top-500 per batch via radix select =================
// sigmoid+bias skipped (strictly monotone => identical ordering / set).
// Only the SET of indices matters downstream (attention symmetric in m, scatter
// order-free); ties at the threshold taken in ascending index order to match lax.top_k.
__global__ void k2_topk() {
    __shared__ unsigned hist[256];
    __shared__ unsigned sh_pref;
    __shared__ int sh_k;
    __shared__ int cntGT, eqcnt;
    __shared__ int eqbuf[1024];

    int b = blockIdx.x, t = threadIdx.x, bd = blockDim.x;
    const float* sc = g_score + b * HWSZ;

    unsigned prefix = 0;
    int k = NPTS;
    for (int byte = 3; byte >= 0; --byte) {
        if (t < 256) hist[t] = 0;
        __syncthreads();
        int shamt = byte * 8;
        for (int i = t; i < HWSZ; i += bd) {
            unsigned u = __float_as_uint(sc[i]);
            u = (u & 0x80000000u) ? ~u : (u | 0x80000000u);
            bool m = (byte == 3) || ((u >> (shamt + 8)) == prefix);
            if (m) atomicAdd(&hist[(u >> shamt) & 255u], 1u);
        }
        __syncthreads();
        if (t == 0) {
            int cum = 0, bin;
            for (bin = 255; bin >= 0; --bin) {
                int h = (int)hist[bin];
                if (cum + h >= k) break;
                cum += h;
            }
            if (bin < 0) bin = 0;  // unreachable safety
            sh_pref = (prefix << 8) | (unsigned)bin;
            sh_k = k - cum;
        }
        __syncthreads();
        prefix = sh_pref; k = sh_k;
        __syncthreads();
    }
    unsigned T = prefix;
    if (t == 0) { cntGT = 0; eqcnt = 0; }
    __syncthreads();
    for (int i = t; i < HWSZ; i += bd) {
        unsigned u = __float_as_uint(sc[i]);
        u = (u & 0x80000000u) ? ~u : (u | 0x80000000u);
        if (u > T) {
            int p = atomicAdd(&cntGT, 1);
            if (p < NPTS) g_idx[b * NPTS + p] = i;
        } else if (u == T) {
            int e = atomicAdd(&eqcnt, 1);
            if (e < 1024) eqbuf[e] = i;
        }
    }
    __syncthreads();
    if (t == 0) {
        int need = k;            // equals to take
        int base = cntGT;        // == NPTS - need by construction
        int ec = eqcnt; if (ec > 1024) ec = 1024;
        if (ec > need) {         // rare: sort ascending, take smallest indices
            for (int a = 1; a < ec; ++a) {
                int v = eqbuf[a]; int jj = a - 1;
                while (jj >= 0 && eqbuf[jj] > v) { eqbuf[jj + 1] = eqbuf[jj]; --jj; }
                eqbuf[jj + 1] = v;
            }
        }
        for (int e = 0; e < need && e < ec && base + e < NPTS; ++e)
            g_idx[b * NPTS + base + e] = eqbuf[e];
    }
}

// ================= kernel 3: patch sampling + mean/max pooling =================
// Grid analysis: the reference's normalized-grid round trip is EXACT in fp32
// (all intermediates are k/256 binary fractions), so px = ix+dx for interior
// points (weight 1) and clamps to +/-0.5-offset border with weight 0.5 per axis.
// One block per (n,b) patch; warp w handles channels w, w+8, ...; lanes cover
// the 49 samples (lane and lane+32), warp-shuffle reduce sum and max.
__global__ void k3_sample(const float* __restrict__ xm, const float* __restrict__ xa) {
    int n = blockIdx.x, b = blockIdx.y;
    int t = threadIdx.x, lane = t & 31, wid = t >> 5;
    int hw = g_idx[b * NPTS + n];
    int iy = hw >> 7, ix = hw & 127;

    int s1 = lane, s2 = lane + 32;
    bool v2 = (s2 < 49);
    int y1 = iy + s1 / 7 - 3, x1 = ix + s1 % 7 - 3;
    int y2 = iy + s2 / 7 - 3, x2 = ix + s2 % 7 - 3;
    float wy1 = 1.f, wx1 = 1.f, wy2 = 1.f, wx2 = 1.f;
    if (y1 < 0) { y1 = 0; wy1 = 0.5f; } else if (y1 > 127) { y1 = 127; wy1 = 0.5f; }
    if (x1 < 0) { x1 = 0; wx1 = 0.5f; } else if (x1 > 127) { x1 = 127; wx1 = 0.5f; }
    if (y2 < 0) { y2 = 0; wy2 = 0.5f; } else if (y2 > 127) { y2 = 127; wy2 = 0.5f; }
    if (x2 < 0) { x2 = 0; wx2 = 0.5f; } else if (x2 > 127) { x2 = 127; wx2 = 0.5f; }
    float w1 = wy1 * wx1, w2 = wy2 * wx2;
    int off1 = y1 * WW + x1, off2 = y2 * WW + x2;
    int outBase = (b * NPTS + n) * CH;

    for (int c = wid; c < CH; c += 8) {
        const float* pm = xm + (size_t)(b * CH + c) * HWSZ;
        const float* pa = xa + (size_t)(b * CH + c) * HWSZ;
        float m1 = pm[off1] * w1;
        float a1 = pa[off1] * w1;
        float m2 = v2 ? pm[off2] * w2 : 0.f;
        float a2 = v2 ? pa[off2] * w2 : 0.f;
        float msum = m1 + m2, asum = a1 + a2;
        float mmax = v2 ? fmaxf(m1, m2) : m1;
        float amax = v2 ? fmaxf(a1, a2) : a1;
        #pragma unroll
        for (int o = 16; o; o >>= 1) {
            msum += __shfl_xor_sync(0xffffffffu, msum, o);
            asum += __shfl_xor_sync(0xffffffffu, asum, o);
            mmax = fmaxf(mmax, __shfl_xor_sync(0xffffffffu, mmax, o));
            amax = fmaxf(amax, __shfl_xor_sync(0xffffffffu, amax, o));
        }
        if (lane == 0) {
            g_vmain[outBase + c] = 0.5f * (msum * (1.f / 49.f) + mmax);
            g_vaux [outBase + c] = 0.5f * (asum * (1.f / 49.f) + amax);
        }
    }
}

// ================= kernel 4: attention + gated MLP + proj =================
// One block per (32-row tile, batch): S[32x500] full tile in SMEM, softmax,
// PV, fc1 folded (z=[vm,vh,vm-vh] => two combined 256x16 weights), gate,
// fused, proj — all fp32 register-tiled.
__global__ void __launch_bounds__(256, 1)
k4_attn(const float* __restrict__ fc1w, const float* __restrict__ fc1b,
        const float* __restrict__ fc2w, const float* __restrict__ fc2b,
        const float* __restrict__ pw,   const float* __restrict__ pb) {
    extern __shared__ float sm[];
    float* Qs = sm;               // [256][36] transposed v_main tile (float4-aligned rows)
    float* Ks = Qs + 256 * 36;    // 8448 floats: K^T tile / V tile / W1a+W1b / proj tile
    float* S  = Ks + 8448;        // [32][504] scores->P ; later Vf[32][257] + W2s
    float* Vh = S + 32 * 504;     // [32][257]

    const int t  = threadIdx.x;
    const int tx = t & 31, ty = t >> 5;
    const int b  = blockIdx.y;
    const int r0 = blockIdx.x * 32;
    const int nrows = min(32, NPTS - r0);

    // ---- load Q (v_main rows) transposed, zero-padded ----
    for (int idx4 = t; idx4 < 32 * 64; idx4 += 256) {
        int r = idx4 >> 6, k4 = (idx4 & 63) * 4;
        float4 v = make_float4(0.f, 0.f, 0.f, 0.f);
        if (r < nrows)
            v = *reinterpret_cast<const float4*>(&g_vmain[(b * NPTS + r0 + r) * CH + k4]);
        Qs[(k4 + 0) * 36 + r] = v.x;
        Qs[(k4 + 1) * 36 + r] = v.y;
        Qs[(k4 + 2) * 36 + r] = v.z;
        Qs[(k4 + 3) * 36 + r] = v.w;
    }
    __syncthreads();

    // ---- S = Q K^T / 16 ----
    for (int mt = 0; mt < 16; ++mt) {
        int m0 = mt * 32;
        int mlim = min(32, NPTS - m0);
        for (int idx4 = t; idx4 < 32 * 64; idx4 += 256) {
            int m = idx4 >> 6, k4 = (idx4 & 63) * 4;
            float4 v = make_float4(0.f, 0.f, 0.f, 0.f);
            if (m < mlim)
                v = *reinterpret_cast<const float4*>(&g_vaux[(b * NPTS + m0 + m) * CH + k4]);
            Ks[(k4 + 0) * 33 + m] = v.x;
            Ks[(k4 + 1) * 33 + m] = v.y;
            Ks[(k4 + 2) * 33 + m] = v.z;
            Ks[(k4 + 3) * 33 + m] = v.w;
        }
        __syncthreads();
        float a0 = 0.f, a1 = 0.f, a2 = 0.f, a3 = 0.f;
        #pragma unroll 8
        for (int k = 0; k < 256; ++k) {
            float4 q = *reinterpret_cast<const float4*>(&Qs[k * 36 + 4 * ty]);
            float kk = Ks[k * 33 + tx];
            a0 += q.x * kk; a1 += q.y * kk; a2 += q.z * kk; a3 += q.w * kk;
        }
        S[(4 * ty + 0) * 504 + m0 + tx] = a0 * 0.0625f;
        S[(4 * ty + 1) * 504 + m0 + tx] = a1 * 0.0625f;
        S[(4 * ty + 2) * 504 + m0 + tx] = a2 * 0.0625f;
        S[(4 * ty + 3) * 504 + m0 + tx] = a3 * 0.0625f;
        __syncthreads();
    }

    // ---- softmax (leave exp in S, keep 1/sum in regs; warp ty owns rows 4ty..4ty+3) ----
    float inv[4];
    #pragma unroll
    for (int i = 0; i < 4; ++i) {
        int r = 4 * ty + i;
        float mx = -CUDART_INF_F;
        for (int m = tx; m < NPTS; m += 32) mx = fmaxf(mx, S[r * 504 + m]);
        #pragma unroll
        for (int o = 16; o; o >>= 1) mx = fmaxf(mx, __shfl_xor_sync(0xffffffffu, mx, o));
        float sum = 0.f;
        for (int m = tx; m < NPTS; m += 32) {
            float e = __expf(S[r * 504 + m] - mx);
            S[r * 504 + m] = e;
            sum += e;
        }
        #pragma unroll
        for (int o = 16; o; o >>= 1) sum += __shfl_xor_sync(0xffffffffu, sum, o);
        inv[i] = 1.f / sum;
    }
    __syncthreads();

    // ---- v_hat = P V  (V tile overlays Ks region, pitch 260 for float4 fills) ----
    float acc[4][8];
    #pragma unroll
    for (int i = 0; i < 4; ++i)
        #pragma unroll
        for (int j = 0; j < 8; ++j) acc[i][j] = 0.f;

    for (int mt = 0; mt < 16; ++mt) {
        int m0 = mt * 32;
        int mlim = min(32, NPTS - m0);
        for (int idx4 = t; idx4 < 32 * 64; idx4 += 256) {
            int m = idx4 >> 6, c4 = (idx4 & 63) * 4;
            float4 v = make_float4(0.f, 0.f, 0.f, 0.f);
            if (m < mlim)
                v = *reinterpret_cast<const float4*>(&g_vaux[(b * NPTS + m0 + m) * CH + c4]);
            *reinterpret_cast<float4*>(&Ks[m * 260 + c4]) = v;
        }
        __syncthreads();
        for (int m = 0; m < mlim; ++m) {
            float p0 = S[(4 * ty + 0) * 504 + m0 + m];
            float p1 = S[(4 * ty + 1) * 504 + m0 + m];
            float p2 = S[(4 * ty + 2) * 504 + m0 + m];
            float p3 = S[(4 * ty + 3) * 504 + m0 + m];
            #pragma unroll
            for (int j = 0; j < 8; ++j) {
                float v = Ks[m * 260 + tx + 32 * j];
                acc[0][j] += p0 * v; acc[1][j] += p1 * v;
                acc[2][j] += p2 * v; acc[3][j] += p3 * v;
            }
        }
        __syncthreads();
    }
    #pragma unroll
    for (int i = 0; i < 4; ++i)
        #pragma unroll
        for (int j = 0; j < 8; ++j)
            Vh[(4 * ty + i) * 257 + tx + 32 * j] = acc[i][j] * inv[i];
    __syncthreads();

    // ---- gated fusion MLP ----
    // z@fc1 with z=[vm,vh,vm-vh]:  h = vm*(W1a+W1c) + vh*(W1b-W1c)
    float* W1a = Ks;            // 256*16
    float* W1b = Ks + 4096;     // 256*16
    float* Vf  = S;             // [32][257]  (P dead)
    float* W2s = S + 8224;      // 16*256
    for (int idx = t; idx < 256 * 16; idx += 256) {
        float wa = fc1w[idx];
        float wb = fc1w[4096 + idx];
        float wc = fc1w[8192 + idx];
        W1a[idx] = wa + wc;
        W1b[idx] = wb - wc;
    }
    for (int idx = t; idx < 4096; idx += 256) W2s[idx] = fc2w[idx];
    __syncthreads();

    int jl = tx & 15, half = tx >> 4;
    float hreg[4];
    #pragma unroll
    for (int i = 0; i < 4; ++i) {
        int r = 4 * ty + i;
        float h = 0.f;
        int k0 = half * 128;
        #pragma unroll 4
        for (int k = k0; k < k0 + 128; ++k) {
            float vm = Qs[k * 36 + r];
            float vh = Vh[r * 257 + k];
            h += vm * W1a[k * 16 + jl] + vh * W1b[k * 16 + jl];
        }
        h += __shfl_xor_sync(0xffffffffu, h, 16);
        h += fc1b[jl];
        hreg[i] = fmaxf(h, 0.f);
    }
    #pragma unroll
    for (int i = 0; i < 4; ++i) {
        int r = 4 * ty + i;
        for (int cb = 0; cb < 256; cb += 32) {
            int c = cb + tx;
            float g = fc2b[c];
            #pragma unroll
            for (int jj = 0; jj < 16; ++jj) {
                float hj = __shfl_sync(0xffffffffu, hreg[i], jj);
                g += hj * W2s[jj * 256 + c];
            }
            g = 1.f / (1.f + __expf(-g));
            float vm = Qs[c * 36 + r];
            float vh = Vh[r * 257 + c];
            Vf[r * 257 + c] = vm + g * (vm - vh);
        }
    }
    __syncthreads();

    // ---- proj: v_inj = Vf @ proj_w + proj_b ----
    float* Pw = Ks;             // [32][260]
    float pacc[4][8];
    #pragma unroll
    for (int i = 0; i < 4; ++i)
        #pragma unroll
        for (int j = 0; j < 8; ++j) pacc[i][j] = 0.f;

    for (int kt = 0; kt < 8; ++kt) {
        int k0 = kt * 32;
        for (int idx4 = t; idx4 < 32 * 64; idx4 += 256) {
            int kk = idx4 >> 6, c4 = (idx4 & 63) * 4;
            float4 v = *reinterpret_cast<const float4*>(&pw[(k0 + kk) * 256 + c4]);
            *reinterpret_cast<float4*>(&Pw[kk * 260 + c4]) = v;
        }
        __syncthreads();
        for (int kk = 0; kk < 32; ++kk) {
            float f0 = Vf[(4 * ty + 0) * 257 + k0 + kk];
            float f1 = Vf[(4 * ty + 1) * 257 + k0 + kk];
            float f2 = Vf[(4 * ty + 2) * 257 + k0 + kk];
            float f3 = Vf[(4 * ty + 3) * 257 + k0 + kk];
            #pragma unroll
            for (int j = 0; j < 8; ++j) {
                float w = Pw[kk * 260 + tx + 32 * j];
                pacc[0][j] += f0 * w; pacc[1][j] += f1 * w;
                pacc[2][j] += f2 * w; pacc[3][j] += f3 * w;
            }
        }
        __syncthreads();
    }
    #pragma unroll
    for (int i = 0; i < 4; ++i) {
        int r = 4 * ty + i;
        if (r < nrows) {
            #pragma unroll
            for (int j = 0; j < 8; ++j) {
                int c = tx + 32 * j;
                g_vinj[(b * NPTS + r0 + r) * CH + c] = pacc[i][j] + pb[c];
            }
        }
    }
}

// ================= kernel 5: scatter-add reinjection =================
// Indices unique within a batch -> conflict-free plain RMW.
__global__ void k5_scatter(float* __restrict__ out) {
    int t = blockIdx.x * 256 + threadIdx.x;
    if (t >= BATCH * NPTS * CH) return;
    int c  = t & 255;
    int bn = t >> 8;
    int n  = bn % NPTS;
    int b  = bn / NPTS;
    int hw = g_idx[b * NPTS + n];
    float* o = out + (size_t)(b * CH + c) * HWSZ + hw;
    *o += g_vinj[t];
}

// ================= launch =================
extern "C" void kernel_launch(void* const* d_in, const int* in_sizes, int n_in,
                              void* d_out, int out_size) {
    const float* xm   = (const float*)d_in[0];
    const float* xa   = (const float*)d_in[1];
    const float* sw   = (const float*)d_in[2];
    // d_in[3] scorer_b: monotone shift, unused for top-k
    const float* fc1w = (const float*)d_in[4];
    const float* fc1b = (const float*)d_in[5];
    const float* fc2w = (const float*)d_in[6];
    const float* fc2b = (const float*)d_in[7];
    const float* pw   = (const float*)d_in[8];
    const float* pb   = (const float*)d_in[9];
    float* out = (float*)d_out;

    const int K4_SMEM = (256 * 36 + 8448 + 32 * 504 + 32 * 257) * 4;  // 168064 B
    cudaFuncSetAttribute(k4_attn, cudaFuncAttributeMaxDynamicSharedMemorySize, K4_SMEM);

    k1_copy_score<<<256, 128>>>(xm, sw, out);
    k2_topk<<<BATCH, 512>>>();
    k3_sample<<<dim3(NPTS, BATCH), 256>>>(xm, xa);
    k4_attn<<<dim3(16, BATCH), 256, K4_SMEM>>>(fc1w, fc1b, fc2w, fc2b, pw, pb);
    k5_scatter<<<(BATCH * NPTS * CH + 255) / 256, 256>>>(out);
}

// round 2
// speedup vs baseline: 1.0636x; 1.0636x over previous
#include <cuda_runtime.h>
#include <math_constants.h>
#include <stdint.h>

#define BATCH 8
#define CH 256
#define HH 128
#define WW 128
#define HWSZ 16384
#define NPTS 500
#define NHID 16

typedef unsigned long long u64;

// ---------------- scratch (device globals; no allocation allowed) ----------------
__device__ float g_score[BATCH * HWSZ];
__device__ float g_spart[8 * BATCH * HWSZ];   // per-channel-chunk partial scores
__device__ int   g_idx[BATCH * NPTS];
__device__ float g_vmain[BATCH * NPTS * CH];
__device__ float g_vaux [BATCH * NPTS * CH];

// ---------------- f32x2 packed-math helpers ----------------
__device__ __forceinline__ u64 pk2(float x, float y) {
    u64 d; asm("mov.b64 %0, {%1, %2};" : "=l"(d) : "f"(x), "f"(y)); return d;
}
__device__ __forceinline__ void upk2(float& x, float& y, u64 d) {
    asm("mov.b64 {%0, %1}, %2;" : "=f"(x), "=f"(y) : "l"(d));
}
__device__ __forceinline__ u64 f2fma(u64 a, u64 b, u64 c) {
    u64 d; asm("fma.rn.f32x2 %0, %1, %2, %3;" : "=l"(d) : "l"(a), "l"(b), "l"(c)); return d;
}
__device__ __forceinline__ u64 f2mul(u64 a, u64 b) {
    u64 d; asm("mul.rn.f32x2 %0, %1, %2;" : "=l"(d) : "l"(a), "l"(b)); return d;
}

// ================= kernel 1: fused copy (out = x_main) + scorer partials =================
// grid (128, 8): blockIdx.y = channel chunk (32 ch). 262144 threads total so the
// 536MB stream can actually saturate HBM. Deterministic partials (no atomics).
__global__ void k1_copy_score(const float* __restrict__ xm,
                              const float* __restrict__ sw,
                              float* __restrict__ out) {
    __shared__ float s_w[32];
    int t = threadIdx.x, chunk = blockIdx.y;
    if (t < 32) s_w[t] = sw[chunk * 32 + t];
    __syncthreads();

    int gp = (blockIdx.x * 256 + t) * 4;     // pixel index in [0, BATCH*HWSZ)
    int b  = gp >> 14;
    int hw = gp & (HWSZ - 1);
    const float4* src = reinterpret_cast<const float4*>(xm + (size_t)(b * CH + chunk * 32) * HWSZ + hw);
    float4*       dst = reinterpret_cast<float4*>(out + (size_t)(b * CH + chunk * 32) * HWSZ + hw);

    float a0 = 0.f, a1 = 0.f, a2 = 0.f, a3 = 0.f;
    #pragma unroll 8
    for (int c = 0; c < 32; ++c) {
        float4 v = src[c * (HWSZ / 4)];
        dst[c * (HWSZ / 4)] = v;
        float w = s_w[c];
        a0 += v.x * w; a1 += v.y * w; a2 += v.z * w; a3 += v.w * w;
    }
    *reinterpret_cast<float4*>(g_spart + (size_t)chunk * BATCH * HWSZ + gp) =
        make_float4(a0, a1, a2, a3);
}

__global__ void k1b_reduce() {
    int i = (blockIdx.x * 256 + threadIdx.x) * 4;
    float4 s = make_float4(0.f, 0.f, 0.f, 0.f);
    #pragma unroll
    for (int ch = 0; ch < 8; ++ch) {
        float4 v = *reinterpret_cast<const float4*>(g_spart + (size_t)ch * BATCH * HWSZ + i);
        s.x += v.x; s.y += v.y; s.z += v.z; s.w += v.w;
    }
    *reinterpret_cast<float4*>(g_score + i) = s;
}

// ================= kernel 2: exact top-500 per batch via radix select =================
__global__ void k2_topk() {
    __shared__ unsigned hist[256];
    __shared__ unsigned sh_pref;
    __shared__ int sh_k;
    __shared__ int cntGT, eqcnt;
    __shared__ int eqbuf[1024];

    int b = blockIdx.x, t = threadIdx.x, bd = blockDim.x;
    const float* sc = g_score + b * HWSZ;

    unsigned prefix = 0;
    int k = NPTS;
    for (int byte = 3; byte >= 0; --byte) {
        if (t < 256) hist[t] = 0;
        __syncthreads();
        int shamt = byte * 8;
        for (int i = t; i < HWSZ; i += bd) {
            unsigned u = __float_as_uint(sc[i]);
            u = (u & 0x80000000u) ? ~u : (u | 0x80000000u);
            bool m = (byte == 3) || ((u >> (shamt + 8)) == prefix);
            if (m) atomicAdd(&hist[(u >> shamt) & 255u], 1u);
        }
        __syncthreads();
        if (t == 0) {
            int cum = 0, bin;
            for (bin = 255; bin >= 0; --bin) {
                int h = (int)hist[bin];
                if (cum + h >= k) break;
                cum += h;
            }
            if (bin < 0) bin = 0;
            sh_pref = (prefix << 8) | (unsigned)bin;
            sh_k = k - cum;
        }
        __syncthreads();
        prefix = sh_pref; k = sh_k;
        __syncthreads();
    }
    unsigned T = prefix;
    if (t == 0) { cntGT = 0; eqcnt = 0; }
    __syncthreads();
    for (int i = t; i < HWSZ; i += bd) {
        unsigned u = __float_as_uint(sc[i]);
        u = (u & 0x80000000u) ? ~u : (u | 0x80000000u);
        if (u > T) {
            int p = atomicAdd(&cntGT, 1);
            if (p < NPTS) g_idx[b * NPTS + p] = i;
        } else if (u == T) {
            int e = atomicAdd(&eqcnt, 1);
            if (e < 1024) eqbuf[e] = i;
        }
    }
    __syncthreads();
    if (t == 0) {
        int need = k;
        int base = cntGT;
        int ec = eqcnt; if (ec > 1024) ec = 1024;
        if (ec > need) {
            for (int a = 1; a < ec; ++a) {
                int v = eqbuf[a]; int jj = a - 1;
                while (jj >= 0 && eqbuf[jj] > v) { eqbuf[jj + 1] = eqbuf[jj]; --jj; }
                eqbuf[jj + 1] = v;
            }
        }
        for (int e = 0; e < need && e < ec && base + e < NPTS; ++e)
            g_idx[b * NPTS + base + e] = eqbuf[e];
    }
}

// ================= kernel 3: patch sampling + mean/max pooling =================
// Exact-grid simplification: interior samples weight 1 at integer coords;
// border clamps contribute weight 0.5 per clamped axis.
__global__ void k3_sample(const float* __restrict__ xm, const float* __restrict__ xa) {
    int n = blockIdx.x, b = blockIdx.y;
    int t = threadIdx.x, lane = t & 31, wid = t >> 5;
    int hw = g_idx[b * NPTS + n];
    int iy = hw >> 7, ix = hw & 127;

    int s1 = lane, s2 = lane + 32;
    bool v2 = (s2 < 49);
    int y1 = iy + s1 / 7 - 3, x1 = ix + s1 % 7 - 3;
    int y2 = iy + s2 / 7 - 3, x2 = ix + s2 % 7 - 3;
    float wy1 = 1.f, wx1 = 1.f, wy2 = 1.f, wx2 = 1.f;
    if (y1 < 0) { y1 = 0; wy1 = 0.5f; } else if (y1 > 127) { y1 = 127; wy1 = 0.5f; }
    if (x1 < 0) { x1 = 0; wx1 = 0.5f; } else if (x1 > 127) { x1 = 127; wx1 = 0.5f; }
    if (y2 < 0) { y2 = 0; wy2 = 0.5f; } else if (y2 > 127) { y2 = 127; wy2 = 0.5f; }
    if (x2 < 0) { x2 = 0; wx2 = 0.5f; } else if (x2 > 127) { x2 = 127; wx2 = 0.5f; }
    float w1 = wy1 * wx1, w2 = wy2 * wx2;
    int off1 = y1 * WW + x1, off2 = y2 * WW + x2;
    int outBase = (b * NPTS + n) * CH;

    for (int c = wid; c < CH; c += 8) {
        const float* pm = xm + (size_t)(b * CH + c) * HWSZ;
        const float* pa = xa + (size_t)(b * CH + c) * HWSZ;
        float m1 = pm[off1] * w1;
        float a1 = pa[off1] * w1;
        float m2 = v2 ? pm[off2] * w2 : 0.f;
        float a2 = v2 ? pa[off2] * w2 : 0.f;
        float msum = m1 + m2, asum = a1 + a2;
        float mmax = v2 ? fmaxf(m1, m2) : m1;
        float amax = v2 ? fmaxf(a1, a2) : a1;
        #pragma unroll
        for (int o = 16; o; o >>= 1) {
            msum += __shfl_xor_sync(0xffffffffu, msum, o);
            asum += __shfl_xor_sync(0xffffffffu, asum, o);
            mmax = fmaxf(mmax, __shfl_xor_sync(0xffffffffu, mmax, o));
            amax = fmaxf(amax, __shfl_xor_sync(0xffffffffu, amax, o));
        }
        if (lane == 0) {
            g_vmain[outBase + c] = 0.5f * (msum * (1.f / 49.f) + mmax);
            g_vaux [outBase + c] = 0.5f * (asum * (1.f / 49.f) + amax);
        }
    }
}

// ================= kernel 4: attention + gated MLP + proj + scatter (f32x2) =================
// smem regions (floats):
//  Qs : [256][36] transposed v_main           at 0      (9216)
//  T  : tile buf Kt[256][33]/Vt[32][260]/W1p/Pw at 9216 (8448)
//  S  : S_t[512][36] -> later Vf_t[256][36]+W2  at 17664 (18432)
//  Vh : [32][260]                              at 36096 (8320)
#define SM_QS 0
#define SM_T  9216
#define SM_S  17664
#define SM_VH 36096
#define SM_TOT 44416

__global__ void __launch_bounds__(256, 1)
k4_attn(const float* __restrict__ fc1w, const float* __restrict__ fc1b,
        const float* __restrict__ fc2w, const float* __restrict__ fc2b,
        const float* __restrict__ pw,   const float* __restrict__ pb,
        float* __restrict__ out) {
    extern __shared__ float sm[];
    float* Qs  = sm + SM_QS;
    float* T   = sm + SM_T;
    float* S_t = sm + SM_S;
    float* Vh  = sm + SM_VH;

    const int t  = threadIdx.x;
    const int tx = t & 31, ty = t >> 5;
    const int b  = blockIdx.y;
    const int r0 = blockIdx.x * 32;
    const int nrows = min(32, NPTS - r0);

    // ---- load Q (v_main rows) transposed, zero-padded ----
    for (int idx4 = t; idx4 < 32 * 64; idx4 += 256) {
        int r = idx4 >> 6, k4 = (idx4 & 63) * 4;
        float4 v = make_float4(0.f, 0.f, 0.f, 0.f);
        if (r < nrows)
            v = *reinterpret_cast<const float4*>(&g_vmain[(b * NPTS + r0 + r) * CH + k4]);
        Qs[(k4 + 0) * 36 + r] = v.x;
        Qs[(k4 + 1) * 36 + r] = v.y;
        Qs[(k4 + 2) * 36 + r] = v.z;
        Qs[(k4 + 3) * 36 + r] = v.w;
    }
    __syncthreads();

    // ---- S = Q K^T / 16, stored transposed S_t[m][r] ----
    for (int mt = 0; mt < 16; ++mt) {
        int m0 = mt * 32;
        int mlim = min(32, NPTS - m0);
        for (int idx4 = t; idx4 < 32 * 64; idx4 += 256) {
            int m = idx4 >> 6, k4 = (idx4 & 63) * 4;
            float4 v = make_float4(0.f, 0.f, 0.f, 0.f);
            if (m < mlim)
                v = *reinterpret_cast<const float4*>(&g_vaux[(b * NPTS + m0 + m) * CH + k4]);
            T[(k4 + 0) * 33 + m] = v.x;
            T[(k4 + 1) * 33 + m] = v.y;
            T[(k4 + 2) * 33 + m] = v.z;
            T[(k4 + 3) * 33 + m] = v.w;
        }
        __syncthreads();
        u64 s01 = pk2(0.f, 0.f), s23 = pk2(0.f, 0.f);
        #pragma unroll 8
        for (int k = 0; k < 256; ++k) {
            ulonglong2 q = *reinterpret_cast<const ulonglong2*>(&Qs[k * 36 + 4 * ty]);
            float kk = T[k * 33 + tx];
            u64 kk2 = pk2(kk, kk);
            s01 = f2fma(q.x, kk2, s01);
            s23 = f2fma(q.y, kk2, s23);
        }
        float a0, a1, a2, a3;
        upk2(a0, a1, s01); upk2(a2, a3, s23);
        *reinterpret_cast<float4*>(&S_t[(m0 + tx) * 36 + 4 * ty]) =
            make_float4(a0 * 0.0625f, a1 * 0.0625f, a2 * 0.0625f, a3 * 0.0625f);
        __syncthreads();
    }

    // ---- softmax over m (rows 4ty..4ty+3 per warp); leave exp in S_t ----
    float inv[4];
    #pragma unroll
    for (int i = 0; i < 4; ++i) {
        int r = 4 * ty + i;
        float mx = -CUDART_INF_F;
        for (int m = tx; m < NPTS; m += 32) mx = fmaxf(mx, S_t[m * 36 + r]);
        #pragma unroll
        for (int o = 16; o; o >>= 1) mx = fmaxf(mx, __shfl_xor_sync(0xffffffffu, mx, o));
        float sum = 0.f;
        for (int m = tx; m < NPTS; m += 32) {
            float e = __expf(S_t[m * 36 + r] - mx);
            S_t[m * 36 + r] = e;
            sum += e;
        }
        #pragma unroll
        for (int o = 16; o; o >>= 1) sum += __shfl_xor_sync(0xffffffffu, sum, o);
        inv[i] = 1.f / sum;
    }
    __syncthreads();

    // ---- v_hat = P V ; acc[i][j2] packs cols (64*j2+2tx, +1) for row 4ty+i ----
    u64 acc[4][4];
    #pragma unroll
    for (int i = 0; i < 4; ++i)
        #pragma unroll
        for (int j = 0; j < 4; ++j) acc[i][j] = pk2(0.f, 0.f);

    for (int mt = 0; mt < 16; ++mt) {
        int m0 = mt * 32;
        int mlim = min(32, NPTS - m0);
        for (int idx4 = t; idx4 < 32 * 64; idx4 += 256) {
            int m = idx4 >> 6, c4 = (idx4 & 63) * 4;
            float4 v = make_float4(0.f, 0.f, 0.f, 0.f);
            if (m < mlim)
                v = *reinterpret_cast<const float4*>(&g_vaux[(b * NPTS + m0 + m) * CH + c4]);
            *reinterpret_cast<float4*>(&T[m * 260 + c4]) = v;
        }
        __syncthreads();
        for (int m = 0; m < mlim; ++m) {
            ulonglong2 pp = *reinterpret_cast<const ulonglong2*>(&S_t[(m0 + m) * 36 + 4 * ty]);
            float p0, p1, p2, p3;
            upk2(p0, p1, pp.x); upk2(p2, p3, pp.y);
            u64 a0 = pk2(p0, p0), a1 = pk2(p1, p1), a2 = pk2(p2, p2), a3 = pk2(p3, p3);
            #pragma unroll
            for (int j = 0; j < 4; ++j) {
                u64 v = *reinterpret_cast<const u64*>(&T[m * 260 + 64 * j + 2 * tx]);
                acc[0][j] = f2fma(a0, v, acc[0][j]);
                acc[1][j] = f2fma(a1, v, acc[1][j]);
                acc[2][j] = f2fma(a2, v, acc[2][j]);
                acc[3][j] = f2fma(a3, v, acc[3][j]);
            }
        }
        __syncthreads();
    }
    #pragma unroll
    for (int i = 0; i < 4; ++i) {
        u64 s = pk2(inv[i], inv[i]);
        #pragma unroll
        for (int j = 0; j < 4; ++j)
            *reinterpret_cast<u64*>(&Vh[(4 * ty + i) * 260 + 64 * j + 2 * tx]) =
                f2mul(acc[i][j], s);
    }
    __syncthreads();

    // ---- stage MLP weights: W1p interleaved (W1a,W1b) in T; W2 in S region ----
    float* W1p  = T;                 // [256][32] interleaved u64 pairs: 8192 floats
    float* Vf_t = S_t;               // [256][36] transposed fused result: 9216 floats
    float* W2s  = S_t + 9216;        // [16][256]: 4096 floats
    for (int idx = t; idx < 256 * 16; idx += 256) {
        int k = idx >> 4, j = idx & 15;
        float wa = fc1w[idx];
        float wb = fc1w[4096 + idx];
        float wc = fc1w[8192 + idx];
        W1p[k * 32 + 2 * j]     = wa + wc;   // coeff for vm
        W1p[k * 32 + 2 * j + 1] = wb - wc;   // coeff for vh
    }
    for (int idx = t; idx < 4096; idx += 256) W2s[idx] = fc2w[idx];
    __syncthreads();

    // ---- fc1: h[j] = sum_k vm*W1a + vh*W1b (packed), split-k over half-warps ----
    int jl = tx & 15, half = tx >> 4;
    float hreg[4];
    #pragma unroll
    for (int i = 0; i < 4; ++i) {
        int r = 4 * ty + i;
        u64 hp = pk2(0.f, 0.f);
        int k0 = half * 128;
        #pragma unroll 4
        for (int k = k0; k < k0 + 128; ++k) {
            float vm = Qs[k * 36 + r];
            float vh = Vh[r * 260 + k];
            u64 w = *reinterpret_cast<const u64*>(&W1p[k * 32 + 2 * jl]);
            hp = f2fma(pk2(vm, vh), w, hp);
        }
        float hx, hy; upk2(hx, hy, hp);
        float h = hx + hy;
        h += __shfl_xor_sync(0xffffffffu, h, 16);
        h += fc1b[jl];
        hreg[i] = fmaxf(h, 0.f);
    }

    // ---- fc2 + sigmoid gate + fuse; write Vf transposed [c][r] ----
    #pragma unroll
    for (int i = 0; i < 4; ++i) {
        int r = 4 * ty + i;
        for (int cb = 0; cb < 256; cb += 32) {
            int c = cb + tx;
            float g = fc2b[c];
            #pragma unroll
            for (int jj = 0; jj < 16; ++jj) {
                float hj = __shfl_sync(0xffffffffu, hreg[i], jj);
                g += hj * W2s[jj * 256 + c];
            }
            g = 1.f / (1.f + __expf(-g));
            float vm = Qs[c * 36 + r];
            float vh = Vh[r * 260 + c];
            Vf_t[c * 36 + r] = vm + g * (vm - vh);
        }
    }
    __syncthreads();

    // ---- proj: v_inj = Vf @ proj_w + proj_b (packed cols, same scheme as PV) ----
    float* Pw = T;                  // [32][260]
    u64 pacc[4][4];
    #pragma unroll
    for (int i = 0; i < 4; ++i)
        #pragma unroll
        for (int j = 0; j < 4; ++j) pacc[i][j] = pk2(0.f, 0.f);

    for (int kt = 0; kt < 8; ++kt) {
        int k0 = kt * 32;
        for (int idx4 = t; idx4 < 32 * 64; idx4 += 256) {
            int kk = idx4 >> 6, c4 = (idx4 & 63) * 4;
            float4 v = *reinterpret_cast<const float4*>(&pw[(k0 + kk) * 256 + c4]);
            *reinterpret_cast<float4*>(&Pw[kk * 260 + c4]) = v;
        }
        __syncthreads();
        for (int kk = 0; kk < 32; ++kk) {
            ulonglong2 ff = *reinterpret_cast<const ulonglong2*>(&Vf_t[(k0 + kk) * 36 + 4 * ty]);
            float f0, f1, f2, f3;
            upk2(f0, f1, ff.x); upk2(f2, f3, ff.y);
            u64 a0 = pk2(f0, f0), a1 = pk2(f1, f1), a2 = pk2(f2, f2), a3 = pk2(f3, f3);
            #pragma unroll
            for (int j = 0; j < 4; ++j) {
                u64 w = *reinterpret_cast<const u64*>(&Pw[kk * 260 + 64 * j + 2 * tx]);
                pacc[0][j] = f2fma(a0, w, pacc[0][j]);
                pacc[1][j] = f2fma(a1, w, pacc[1][j]);
                pacc[2][j] = f2fma(a2, w, pacc[2][j]);
                pacc[3][j] = f2fma(a3, w, pacc[3][j]);
            }
        }
        __syncthreads();
    }

    // ---- epilogue: scatter-add directly into out (indices unique per batch) ----
    #pragma unroll
    for (int i = 0; i < 4; ++i) {
        int r = 4 * ty + i;
        if (r < nrows) {
            int hw = g_idx[b * NPTS + r0 + r];
            float* ob = out + (size_t)b * CH * HWSZ + hw;
            #pragma unroll
            for (int j = 0; j < 4; ++j) {
                int c = 64 * j + 2 * tx;
                float v0, v1; upk2(v0, v1, pacc[i][j]);
                ob[(size_t)c * HWSZ]       += v0 + pb[c];
                ob[(size_t)(c + 1) * HWSZ] += v1 + pb[c + 1];
            }
        }
    }
}

// ================= launch =================
extern "C" void kernel_launch(void* const* d_in, const int* in_sizes, int n_in,
                              void* d_out, int out_size) {
    const float* xm   = (const float*)d_in[0];
    const float* xa   = (const float*)d_in[1];
    const float* sw   = (const float*)d_in[2];
    // d_in[3] scorer_b: monotone shift, irrelevant to top-k
    const float* fc1w = (const float*)d_in[4];
    const float* fc1b = (const float*)d_in[5];
    const float* fc2w = (const float*)d_in[6];
    const float* fc2b = (const float*)d_in[7];
    const float* pw   = (const float*)d_in[8];
    const float* pb   = (const float*)d_in[9];
    float* out = (float*)d_out;

    const int K4_SMEM = SM_TOT * 4;   // 177664 B
    cudaFuncSetAttribute(k4_attn, cudaFuncAttributeMaxDynamicSharedMemorySize, K4_SMEM);

    k1_copy_score<<<dim3(128, 8), 256>>>(xm, sw, out);
    k1b_reduce<<<128, 256>>>();
    k2_topk<<<BATCH, 512>>>();
    k3_sample<<<dim3(NPTS, BATCH), 256>>>(xm, xa);
    k4_attn<<<dim3(16, BATCH), 256, K4_SMEM>>>(fc1w, fc1b, fc2w, fc2b, pw, pb, out);
}

// round 3
// speedup vs baseline: 1.1938x; 1.1225x over previous
#include <cuda_runtime.h>
#include <math_constants.h>
#include <stdint.h>

#define BATCH 8
#define CH 256
#define HH 128
#define WW 128
#define HWSZ 16384
#define NPTS 500
#define NPAD 512
#define NHID 16

typedef unsigned long long u64;

// ---------------- scratch (device globals; no allocation allowed) ----------------
__device__ float g_score[BATCH * HWSZ];
__device__ float g_spart[8 * BATCH * HWSZ];
__device__ int   g_idx[BATCH * NPTS];
__device__ float g_vmt [BATCH * CH * NPAD];   // v_main transposed [b][c][n], zero-padded
__device__ float g_vat [BATCH * CH * NPAD];   // v_aux  transposed [b][c][n]
__device__ float g_vaux[BATCH * NPTS * CH];   // v_aux row-major [b][n][c]

// ---------------- f32x2 packed-math helpers ----------------
__device__ __forceinline__ u64 pk2(float x, float y) {
    u64 d; asm("mov.b64 %0, {%1, %2};" : "=l"(d) : "f"(x), "f"(y)); return d;
}
__device__ __forceinline__ void upk2(float& x, float& y, u64 d) {
    asm("mov.b64 {%0, %1}, %2;" : "=f"(x), "=f"(y) : "l"(d));
}
__device__ __forceinline__ u64 f2fma(u64 a, u64 b, u64 c) {
    u64 d; asm("fma.rn.f32x2 %0, %1, %2, %3;" : "=l"(d) : "l"(a), "l"(b), "l"(c)); return d;
}
__device__ __forceinline__ u64 f2mul(u64 a, u64 b) {
    u64 d; asm("mul.rn.f32x2 %0, %1, %2;" : "=l"(d) : "l"(a), "l"(b)); return d;
}

// ================= kernel 1: fused copy (out = x_main) + scorer partials =================
__global__ void k1_copy_score(const float* __restrict__ xm,
                              const float* __restrict__ sw,
                              float* __restrict__ out) {
    __shared__ float s_w[32];
    int t = threadIdx.x, chunk = blockIdx.y;
    if (t < 32) s_w[t] = sw[chunk * 32 + t];
    __syncthreads();

    int gp = (blockIdx.x * 256 + t) * 4;
    int b  = gp >> 14;
    int hw = gp & (HWSZ - 1);
    const float4* src = reinterpret_cast<const float4*>(xm + (size_t)(b * CH + chunk * 32) * HWSZ + hw);
    float4*       dst = reinterpret_cast<float4*>(out + (size_t)(b * CH + chunk * 32) * HWSZ + hw);

    float a0 = 0.f, a1 = 0.f, a2 = 0.f, a3 = 0.f;
    #pragma unroll 8
    for (int c = 0; c < 32; ++c) {
        float4 v = src[c * (HWSZ / 4)];
        dst[c * (HWSZ / 4)] = v;
        float w = s_w[c];
        a0 += v.x * w; a1 += v.y * w; a2 += v.z * w; a3 += v.w * w;
    }
    *reinterpret_cast<float4*>(g_spart + (size_t)chunk * BATCH * HWSZ + gp) =
        make_float4(a0, a1, a2, a3);
}

__global__ void k1b_reduce() {
    int i = (blockIdx.x * 256 + threadIdx.x) * 4;
    float4 s = make_float4(0.f, 0.f, 0.f, 0.f);
    #pragma unroll
    for (int ch = 0; ch < 8; ++ch) {
        float4 v = *reinterpret_cast<const float4*>(g_spart + (size_t)ch * BATCH * HWSZ + i);
        s.x += v.x; s.y += v.y; s.z += v.z; s.w += v.w;
    }
    *reinterpret_cast<float4*>(g_score + i) = s;
}

// ================= kernel 2: exact top-500 per batch via radix select =================
__global__ void k2_topk() {
    __shared__ unsigned hist[256];
    __shared__ unsigned sh_pref;
    __shared__ int sh_k;
    __shared__ int cntGT, eqcnt;
    __shared__ int eqbuf[1024];

    int b = blockIdx.x, t = threadIdx.x, bd = blockDim.x;
    const float* sc = g_score + b * HWSZ;

    unsigned prefix = 0;
    int k = NPTS;
    for (int byte = 3; byte >= 0; --byte) {
        if (t < 256) hist[t] = 0;
        __syncthreads();
        int shamt = byte * 8;
        for (int i = t; i < HWSZ; i += bd) {
            unsigned u = __float_as_uint(sc[i]);
            u = (u & 0x80000000u) ? ~u : (u | 0x80000000u);
            bool m = (byte == 3) || ((u >> (shamt + 8)) == prefix);
            if (m) atomicAdd(&hist[(u >> shamt) & 255u], 1u);
        }
        __syncthreads();
        if (t == 0) {
            int cum = 0, bin;
            for (bin = 255; bin >= 0; --bin) {
                int h = (int)hist[bin];
                if (cum + h >= k) break;
                cum += h;
            }
            if (bin < 0) bin = 0;
            sh_pref = (prefix << 8) | (unsigned)bin;
            sh_k = k - cum;
        }
        __syncthreads();
        prefix = sh_pref; k = sh_k;
        __syncthreads();
    }
    unsigned T = prefix;
    if (t == 0) { cntGT = 0; eqcnt = 0; }
    __syncthreads();
    for (int i = t; i < HWSZ; i += bd) {
        unsigned u = __float_as_uint(sc[i]);
        u = (u & 0x80000000u) ? ~u : (u | 0x80000000u);
        if (u > T) {
            int p = atomicAdd(&cntGT, 1);
            if (p < NPTS) g_idx[b * NPTS + p] = i;
        } else if (u == T) {
            int e = atomicAdd(&eqcnt, 1);
            if (e < 1024) eqbuf[e] = i;
        }
    }
    __syncthreads();
    if (t == 0) {
        int need = k;
        int base = cntGT;
        int ec = eqcnt; if (ec > 1024) ec = 1024;
        if (ec > need) {
            for (int a = 1; a < ec; ++a) {
                int v = eqbuf[a]; int jj = a - 1;
                while (jj >= 0 && eqbuf[jj] > v) { eqbuf[jj + 1] = eqbuf[jj]; --jj; }
                eqbuf[jj + 1] = v;
            }
        }
        for (int e = 0; e < need && e < ec && base + e < NPTS; ++e)
            g_idx[b * NPTS + base + e] = eqbuf[e];
    }
}

// ================= kernel 3: stream channel plane -> pool patches from smem =================
// One block per (b,c): coalesced 64KB plane load into smem, then each thread pools
// whole patches (exact-grid: interior weight 1, clamped axis weight 0.5).
__global__ void __launch_bounds__(256) k3_pool(const float* __restrict__ xm,
                                               const float* __restrict__ xa) {
    extern __shared__ float sp[];          // [HWSZ] plane, then int s_hw[NPTS]
    int* s_hw = (int*)(sp + HWSZ);
    int c = blockIdx.x, b = blockIdx.y, t = threadIdx.x;

    for (int i = t; i < NPTS; i += 256) s_hw[i] = g_idx[b * NPTS + i];

    #pragma unroll
    for (int s = 0; s < 2; ++s) {
        const float* src = (s == 0 ? xm : xa) + (size_t)(b * CH + c) * HWSZ;
        __syncthreads();
        for (int i = t; i < HWSZ / 4; i += 256)
            reinterpret_cast<float4*>(sp)[i] = reinterpret_cast<const float4*>(src)[i];
        __syncthreads();

        for (int p = t; p < NPTS; p += 256) {
            int hw = s_hw[p];
            int iy = hw >> 7, ix = hw & 127;
            float sum = 0.f, mx = -CUDART_INF_F;
            if (iy >= 3 && iy <= 124 && ix >= 3 && ix <= 124) {
                const float* base = sp + (iy - 3) * WW + (ix - 3);
                #pragma unroll
                for (int dy = 0; dy < 7; ++dy) {
                    #pragma unroll
                    for (int dx = 0; dx < 7; ++dx) {
                        float v = base[dy * WW + dx];
                        sum += v; mx = fmaxf(mx, v);
                    }
                }
            } else {
                #pragma unroll
                for (int dy = -3; dy <= 3; ++dy) {
                    int yy = iy + dy; float wy = 1.f;
                    if (yy < 0) { yy = 0; wy = 0.5f; } else if (yy > 127) { yy = 127; wy = 0.5f; }
                    #pragma unroll
                    for (int dx = -3; dx <= 3; ++dx) {
                        int xx = ix + dx; float wx = wy;
                        if (xx < 0) { xx = 0; wx *= 0.5f; } else if (xx > 127) { xx = 127; wx *= 0.5f; }
                        float v = sp[yy * WW + xx] * wx;
                        sum += v; mx = fmaxf(mx, v);
                    }
                }
            }
            float r = 0.5f * (sum * (1.f / 49.f) + mx);
            if (s == 0) {
                g_vmt[(b * CH + c) * NPAD + p] = r;
            } else {
                g_vat[(b * CH + c) * NPAD + p] = r;
                g_vaux[(b * NPTS + p) * CH + c] = r;
            }
        }
    }
}

// ================= kernel 4: attention + gated MLP + proj + scatter (f32x2) =================
// smem (floats): Qs[256][36] @0 ; T (K tile [256][36] / V tile [32][260] / W1p / Pw) @9216 ;
//                S_t[512][36] -> Vf_t[256][36]+W2s @18432 ; Vh[32][260] @36864
#define SM_QS 0
#define SM_T  9216
#define SM_S  18432
#define SM_VH 36864
#define SM_TOT 45184

__global__ void __launch_bounds__(256, 1)
k4_attn(const float* __restrict__ fc1w, const float* __restrict__ fc1b,
        const float* __restrict__ fc2w, const float* __restrict__ fc2b,
        const float* __restrict__ pw,   const float* __restrict__ pb,
        float* __restrict__ out) {
    extern __shared__ float sm[];
    float* Qs  = sm + SM_QS;
    float* T   = sm + SM_T;
    float* S_t = sm + SM_S;
    float* Vh  = sm + SM_VH;

    const int t  = threadIdx.x;
    const int tx = t & 31, ty = t >> 5;
    const int b  = blockIdx.y;
    const int r0 = blockIdx.x * 32;
    const int nrows = min(32, NPTS - r0);

    // ---- load Q transposed tile straight from g_vmt (float4 both sides) ----
    for (int idx4 = t; idx4 < 2048; idx4 += 256) {
        int k = idx4 >> 3, i4 = (idx4 & 7) * 4;
        float4 v = *reinterpret_cast<const float4*>(&g_vmt[(b * CH + k) * NPAD + r0 + i4]);
        *reinterpret_cast<float4*>(&Qs[k * 36 + i4]) = v;
    }
    __syncthreads();

    // ---- S = Q K^T / 16, stored transposed S_t[m][r] ----
    for (int mt = 0; mt < 16; ++mt) {
        int m0 = mt * 32;
        for (int idx4 = t; idx4 < 2048; idx4 += 256) {
            int k = idx4 >> 3, i4 = (idx4 & 7) * 4;
            float4 v = *reinterpret_cast<const float4*>(&g_vat[(b * CH + k) * NPAD + m0 + i4]);
            *reinterpret_cast<float4*>(&T[k * 36 + i4]) = v;
        }
        __syncthreads();
        u64 s01 = pk2(0.f, 0.f), s23 = pk2(0.f, 0.f);
        #pragma unroll 8
        for (int k = 0; k < 256; ++k) {
            ulonglong2 q = *reinterpret_cast<const ulonglong2*>(&Qs[k * 36 + 4 * ty]);
            float kk = T[k * 36 + tx];
            u64 kk2 = pk2(kk, kk);
            s01 = f2fma(q.x, kk2, s01);
            s23 = f2fma(q.y, kk2, s23);
        }
        float a0, a1, a2, a3;
        upk2(a0, a1, s01); upk2(a2, a3, s23);
        *reinterpret_cast<float4*>(&S_t[(m0 + tx) * 36 + 4 * ty]) =
            make_float4(a0 * 0.0625f, a1 * 0.0625f, a2 * 0.0625f, a3 * 0.0625f);
        __syncthreads();
    }

    // ---- softmax over m (rows 4ty..4ty+3 per warp); leave exp in S_t ----
    float inv[4];
    #pragma unroll
    for (int i = 0; i < 4; ++i) {
        int r = 4 * ty + i;
        float mx = -CUDART_INF_F;
        for (int m = tx; m < NPTS; m += 32) mx = fmaxf(mx, S_t[m * 36 + r]);
        #pragma unroll
        for (int o = 16; o; o >>= 1) mx = fmaxf(mx, __shfl_xor_sync(0xffffffffu, mx, o));
        float sum = 0.f;
        for (int m = tx; m < NPTS; m += 32) {
            float e = __expf(S_t[m * 36 + r] - mx);
            S_t[m * 36 + r] = e;
            sum += e;
        }
        #pragma unroll
        for (int o = 16; o; o >>= 1) sum += __shfl_xor_sync(0xffffffffu, sum, o);
        inv[i] = 1.f / sum;
    }
    __syncthreads();

    // ---- v_hat = P V ; acc[i][j] packs cols (64j+2tx, +1) for row 4ty+i ----
    u64 acc[4][4];
    #pragma unroll
    for (int i = 0; i < 4; ++i)
        #pragma unroll
        for (int j = 0; j < 4; ++j) acc[i][j] = pk2(0.f, 0.f);

    for (int mt = 0; mt < 16; ++mt) {
        int m0 = mt * 32;
        int mlim = min(32, NPTS - m0);
        for (int idx4 = t; idx4 < 2048; idx4 += 256) {
            int m = idx4 >> 6, c4 = (idx4 & 63) * 4;
            float4 v = make_float4(0.f, 0.f, 0.f, 0.f);
            if (m < mlim)
                v = *reinterpret_cast<const float4*>(&g_vaux[(b * NPTS + m0 + m) * CH + c4]);
            *reinterpret_cast<float4*>(&T[m * 260 + c4]) = v;
        }
        __syncthreads();
        for (int m = 0; m < mlim; ++m) {
            ulonglong2 pp = *reinterpret_cast<const ulonglong2*>(&S_t[(m0 + m) * 36 + 4 * ty]);
            float p0, p1, p2, p3;
            upk2(p0, p1, pp.x); upk2(p2, p3, pp.y);
            u64 a0 = pk2(p0, p0), a1 = pk2(p1, p1), a2 = pk2(p2, p2), a3 = pk2(p3, p3);
            #pragma unroll
            for (int j = 0; j < 4; ++j) {
                u64 v = *reinterpret_cast<const u64*>(&T[m * 260 + 64 * j + 2 * tx]);
                acc[0][j] = f2fma(a0, v, acc[0][j]);
                acc[1][j] = f2fma(a1, v, acc[1][j]);
                acc[2][j] = f2fma(a2, v, acc[2][j]);
                acc[3][j] = f2fma(a3, v, acc[3][j]);
            }
        }
        __syncthreads();
    }
    #pragma unroll
    for (int i = 0; i < 4; ++i) {
        u64 s = pk2(inv[i], inv[i]);
        #pragma unroll
        for (int j = 0; j < 4; ++j)
            *reinterpret_cast<u64*>(&Vh[(4 * ty + i) * 260 + 64 * j + 2 * tx]) =
                f2mul(acc[i][j], s);
    }
    __syncthreads();

    // ---- stage MLP weights ----
    float* W1p  = T;                 // [256][32] interleaved (W1a,W1b)
    float* Vf_t = S_t;               // [256][36]
    float* W2s  = S_t + 9216;        // [16][256]
    for (int idx = t; idx < 256 * 16; idx += 256) {
        int k = idx >> 4, j = idx & 15;
        float wa = fc1w[idx];
        float wb = fc1w[4096 + idx];
        float wc = fc1w[8192 + idx];
        W1p[k * 32 + 2 * j]     = wa + wc;
        W1p[k * 32 + 2 * j + 1] = wb - wc;
    }
    for (int idx = t; idx < 4096; idx += 256) W2s[idx] = fc2w[idx];
    __syncthreads();

    // ---- fc1 (packed, split-k over half-warps) ----
    int jl = tx & 15, half = tx >> 4;
    float hreg[4];
    #pragma unroll
    for (int i = 0; i < 4; ++i) {
        int r = 4 * ty + i;
        u64 hp = pk2(0.f, 0.f);
        int k0 = half * 128;
        #pragma unroll 4
        for (int k = k0; k < k0 + 128; ++k) {
            float vm = Qs[k * 36 + r];
            float vh = Vh[r * 260 + k];
            u64 w = *reinterpret_cast<const u64*>(&W1p[k * 32 + 2 * jl]);
            hp = f2fma(pk2(vm, vh), w, hp);
        }
        float hx, hy; upk2(hx, hy, hp);
        float h = hx + hy;
        h += __shfl_xor_sync(0xffffffffu, h, 16);
        h += fc1b[jl];
        hreg[i] = fmaxf(h, 0.f);
    }

    // ---- fc2 + sigmoid gate + fuse; write Vf transposed [c][r] ----
    #pragma unroll
    for (int i = 0; i < 4; ++i) {
        int r = 4 * ty + i;
        for (int cb = 0; cb < 256; cb += 32) {
            int c = cb + tx;
            float g = fc2b[c];
            #pragma unroll
            for (int jj = 0; jj < 16; ++jj) {
                float hj = __shfl_sync(0xffffffffu, hreg[i], jj);
                g += hj * W2s[jj * 256 + c];
            }
            g = 1.f / (1.f + __expf(-g));
            float vm = Qs[c * 36 + r];
            float vh = Vh[r * 260 + c];
            Vf_t[c * 36 + r] = vm + g * (vm - vh);
        }
    }
    __syncthreads();

    // ---- proj: v_inj = Vf @ proj_w + proj_b ----
    float* Pw = T;                  // [32][260]
    u64 pacc[4][4];
    #pragma unroll
    for (int i = 0; i < 4; ++i)
        #pragma unroll
        for (int j = 0; j < 4; ++j) pacc[i][j] = pk2(0.f, 0.f);

    for (int kt = 0; kt < 8; ++kt) {
        int k0 = kt * 32;
        for (int idx4 = t; idx4 < 2048; idx4 += 256) {
            int kk = idx4 >> 6, c4 = (idx4 & 63) * 4;
            float4 v = *reinterpret_cast<const float4*>(&pw[(k0 + kk) * 256 + c4]);
            *reinterpret_cast<float4*>(&Pw[kk * 260 + c4]) = v;
        }
        __syncthreads();
        for (int kk = 0; kk < 32; ++kk) {
            ulonglong2 ff = *reinterpret_cast<const ulonglong2*>(&Vf_t[(k0 + kk) * 36 + 4 * ty]);
            float f0, f1, f2, f3;
            upk2(f0, f1, ff.x); upk2(f2, f3, ff.y);
            u64 a0 = pk2(f0, f0), a1 = pk2(f1, f1), a2 = pk2(f2, f2), a3 = pk2(f3, f3);
            #pragma unroll
            for (int j = 0; j < 4; ++j) {
                u64 w = *reinterpret_cast<const u64*>(&Pw[kk * 260 + 64 * j + 2 * tx]);
                pacc[0][j] = f2fma(a0, w, pacc[0][j]);
                pacc[1][j] = f2fma(a1, w, pacc[1][j]);
                pacc[2][j] = f2fma(a2, w, pacc[2][j]);
                pacc[3][j] = f2fma(a3, w, pacc[3][j]);
            }
        }
        __syncthreads();
    }

    // ---- epilogue: scatter-add into out (indices unique per batch) ----
    #pragma unroll
    for (int i = 0; i < 4; ++i) {
        int r = 4 * ty + i;
        if (r < nrows) {
            int hw = g_idx[b * NPTS + r0 + r];
            float* ob = out + (size_t)b * CH * HWSZ + hw;
            #pragma unroll
            for (int j = 0; j < 4; ++j) {
                int c = 64 * j + 2 * tx;
                float v0, v1; upk2(v0, v1, pacc[i][j]);
                ob[(size_t)c * HWSZ]       += v0 + pb[c];
                ob[(size_t)(c + 1) * HWSZ] += v1 + pb[c + 1];
            }
        }
    }
}

// ================= launch =================
extern "C" void kernel_launch(void* const* d_in, const int* in_sizes, int n_in,
                              void* d_out, int out_size) {
    const float* xm   = (const float*)d_in[0];
    const float* xa   = (const float*)d_in[1];
    const float* sw   = (const float*)d_in[2];
    const float* fc1w = (const float*)d_in[4];
    const float* fc1b = (const float*)d_in[5];
    const float* fc2w = (const float*)d_in[6];
    const float* fc2b = (const float*)d_in[7];
    const float* pw   = (const float*)d_in[8];
    const float* pb   = (const float*)d_in[9];
    float* out = (float*)d_out;

    const int K3_SMEM = HWSZ * 4 + NPTS * 4;        // 67536 B
    const int K4_SMEM = SM_TOT * 4;                 // 180736 B
    cudaFuncSetAttribute(k3_pool, cudaFuncAttributeMaxDynamicSharedMemorySize, K3_SMEM);
    cudaFuncSetAttribute(k4_attn, cudaFuncAttributeMaxDynamicSharedMemorySize, K4_SMEM);

    k1_copy_score<<<dim3(128, 8), 256>>>(xm, sw, out);
    k1b_reduce<<<128, 256>>>();
    k2_topk<<<BATCH, 512>>>();
    k3_pool<<<dim3(CH, BATCH), 256, K3_SMEM>>>(xm, xa);
    k4_attn<<<dim3(16, BATCH), 256, K4_SMEM>>>(fc1w, fc1b, fc2w, fc2b, pw, pb, out);
}